// round 12
// baseline (speedup 1.0000x reference)
#include <cuda_runtime.h>
#include <cuda_bf16.h>
#include <cstdint>

// tcgen05 is arch-SPECIFIC (sm_103a): guard device code so the harness's plain
// compute_103 PTX pass compiles. The sm_103a cubin is what actually runs.
#if defined(__CUDA_ARCH__) && (defined(__CUDA_ARCH_FEAT_SM103_ALL) || \
    defined(__CUDA_ARCH_FEAT_SM100_ALL) || defined(__CUDA_ARCH_SPECIFIC__) || \
    defined(__CUDA_ARCH_FAMILY_SPECIFIC__))
#define HAS_TCGEN05 1
#else
#define HAS_TCGEN05 0
#endif

// Problem dims (fixed)
#define B_  8
#define S_  1024
#define D_  1024
#define R_  256

#define TILE_M 128
#define TN     256
#define KCH    64          // bf16 K per chunk = 128B SW128 row
#define ST     2

// ---------------- tiled scratch (device globals; no allocs allowed) ----------
// All operands tile-contiguous + SW128-pre-swizzled:
//   A layout: [row/128][kc][128 rows x 128B]  (16 KB blocks)
//   B layout: [row/256][kc][256 rows x 128B]  (32 KB blocks)
__device__ char g_batch_hi[(size_t)B_*S_*D_*2];   // A for GEMM1/2 (16 MB)
__device__ char g_batch_lo[(size_t)B_*S_*D_*2];
__device__ char g_LT_hi[(size_t)R_*D_*2];         // B for GEMM1 (proj_L^T)
__device__ char g_LT_lo[(size_t)R_*D_*2];
__device__ char g_PR_hi[(size_t)R_*D_*2];         // B for GEMM2 (proj_R)
__device__ char g_PR_lo[(size_t)R_*D_*2];
__device__ char g_left_hi[(size_t)B_*S_*R_*2];    // A for GEMM3 (4 MB)
__device__ char g_left_lo[(size_t)B_*S_*R_*2];
__device__ char g_right_hi[(size_t)B_*S_*R_*2];   // B for GEMM3
__device__ char g_right_lo[(size_t)B_*S_*R_*2];

// ---------------- PTX helpers ----------------
__device__ __forceinline__ uint32_t smem_u32(const void* p) {
    uint32_t a;
    asm("{ .reg .u64 t; cvta.to.shared.u64 t, %1; cvt.u32.u64 %0, t; }" : "=r"(a) : "l"(p));
    return a;
}
#define SW128(off) ((off) ^ (((off) >> 3) & 0x70))

__device__ __forceinline__ void mbar_init(uint32_t a, uint32_t cnt) {
    asm volatile("mbarrier.init.shared.b64 [%0], %1;" :: "r"(a), "r"(cnt) : "memory");
}
__device__ __forceinline__ void mbar_wait(uint32_t a, uint32_t parity) {
    asm volatile(
        "{\n\t.reg .pred P;\n\t"
        "WL_%=:\n\t"
        "mbarrier.try_wait.parity.acquire.cta.shared::cta.b64 P, [%0], %1, 0x989680;\n\t"
        "@P bra WD_%=;\n\t"
        "bra WL_%=;\n\t"
        "WD_%=:\n\t}"
        :: "r"(a), "r"(parity) : "memory");
}

#if HAS_TCGEN05
__device__ __forceinline__ uint32_t elect_one() {
    uint32_t p;
    asm volatile("{ .reg .pred p; elect.sync _|p, 0xFFFFFFFF; selp.b32 %0,1,0,p; }" : "=r"(p));
    return p;
}
__device__ __forceinline__ uint32_t ctarank() {
    uint32_t r;
    asm("mov.u32 %0, %%cluster_ctarank;" : "=r"(r));
    return r;
}
#define CLUSTER_SYNC() do { \
    asm volatile("barrier.cluster.arrive.aligned;" ::: "memory"); \
    asm volatile("barrier.cluster.wait.aligned;" ::: "memory"); \
} while (0)

__device__ __forceinline__ void mbar_expect_tx(uint32_t mbar, uint32_t bytes) {
    asm volatile("mbarrier.arrive.expect_tx.shared.b64 _, [%0], %1;"
                 :: "r"(mbar), "r"(bytes) : "memory");
}
// 1D bulk copy global->smem (own CTA), completion via mbarrier tx-count
__device__ __forceinline__ void bulk_g2s(uint32_t sdst, const void* gsrc,
                                         uint32_t bytes, uint32_t mbar) {
    asm volatile(
        "cp.async.bulk.shared::cluster.global.mbarrier::complete_tx::bytes "
        "[%0], [%1], %2, [%3];"
        :: "r"(sdst), "l"(gsrc), "r"(bytes), "r"(mbar) : "memory");
}
// Multicast variant: delivers data + complete_tx at same offset in every
// cluster CTA in ctaMask. L2/LTS dedups the fetch.
__device__ __forceinline__ void bulk_g2s_mc(uint32_t sdst, const void* gsrc,
                                            uint32_t bytes, uint32_t mbar,
                                            uint16_t mask) {
    asm volatile(
        "cp.async.bulk.shared::cluster.global.mbarrier::complete_tx::bytes"
        ".multicast::cluster [%0], [%1], %2, [%3], %4;"
        :: "r"(sdst), "l"(gsrc), "r"(bytes), "r"(mbar), "h"(mask) : "memory");
}

// SW128 K-major SMEM descriptor (layout=2, version=1, SBO=64, LBO=1)
__device__ __forceinline__ uint64_t make_desc(uint32_t addr) {
    const uint64_t base = (uint64_t(2) << 61) | (uint64_t(1) << 46)
                        | (uint64_t(64) << 32) | (uint64_t(1) << 16);
    return base | ((uint64_t)(addr >> 4) & 0x3FFF);
}
__device__ __forceinline__ void mma_bf16_ss(uint32_t d, uint64_t ad, uint64_t bd,
                                            uint32_t idesc, bool acc) {
    uint32_t en = acc ? 1u : 0u, z = 0u;
    asm volatile(
        "{\n\t.reg .pred p;\n\tsetp.ne.u32 p, %5, 0;\n\t"
        "tcgen05.mma.cta_group::1.kind::f16 [%0], %1, %2, %3, {%4,%4,%4,%4}, p;\n\t}"
        :: "r"(d), "l"(ad), "l"(bd), "r"(idesc), "r"(z), "r"(en) : "memory");
}
__device__ __forceinline__ void tc_commit(uint32_t mbar) {
    asm volatile(
        "tcgen05.commit.cta_group::1.mbarrier::arrive::one.shared::cluster.b64 [%0];"
        :: "r"(mbar) : "memory");
}
// On MMA completion, arrive on the same-offset mbarrier in every masked CTA.
__device__ __forceinline__ void tc_commit_mc(uint32_t mbar, uint16_t mask) {
    asm volatile(
        "tcgen05.commit.cta_group::1.mbarrier::arrive::one.shared::cluster"
        ".multicast::cluster.b64 [%0], %1;"
        :: "r"(mbar), "h"(mask) : "memory");
}
#endif  // HAS_TCGEN05

// ---------------- conversion kernels (emit tiled+swizzled layout) -----------
__device__ __forceinline__ void split1(float v, __nv_bfloat16& h, __nv_bfloat16& l) {
    h = __float2bfloat16_rn(v);
    l = __float2bfloat16_rn(v - __bfloat162float(h));
}

// Row-major (rows x K) fp32 -> tiled/swizzled bf16 hi/lo. TS = tile row count.
template <int TS, int K>
__global__ void split_tiled(const float4* __restrict__ src,
                            char* __restrict__ hi, char* __restrict__ lo) {
    int i = blockIdx.x * blockDim.x + threadIdx.x;
    int idx4 = i * 4;
    int m = idx4 / K, d = idx4 % K;
    float4 v = src[i];
    __nv_bfloat16 h[4], l[4];
    split1(v.x, h[0], l[0]); split1(v.y, h[1], l[1]);
    split1(v.z, h[2], l[2]); split1(v.w, h[3], l[3]);
    uint32_t byteoff = (uint32_t)(d & 63) * 2;                  // multiple of 8
    uint32_t inb = SW128((uint32_t)(m % TS) * 128 + (byteoff & ~15u)) + (byteoff & 15u);
    size_t off = ((size_t)(m / TS) * (K / 64) + (d >> 6)) * ((size_t)TS * 128) + inb;
    *(uint64_t*)(hi + off) = *(const uint64_t*)h;
    *(uint64_t*)(lo + off) = *(const uint64_t*)l;
}

// proj_L (D,R) -> transposed (R,D) tiled/swizzled B layout (TS=256)
__global__ void tsplit_kernel(const float* __restrict__ src,
                              char* __restrict__ hi, char* __restrict__ lo) {
    __shared__ float t[32][33];
    int tx = threadIdx.x, ty = threadIdx.y;
    int d0 = blockIdx.y * 32, r0 = blockIdx.x * 32;
    t[ty][tx] = src[(size_t)(d0 + ty) * R_ + r0 + tx];
    __syncthreads();
    float v = t[tx][ty];                // out[r0+ty][d0+tx]
    int r = r0 + ty, d = d0 + tx;
    __nv_bfloat16 h, l; split1(v, h, l);
    uint32_t byteoff = (uint32_t)(d & 63) * 2;
    size_t off = ((size_t)(r >> 8) * (D_ / 64) + (d >> 6)) * (256u * 64u * 2u)
               + SW128((uint32_t)(r & 255) * 128 + (byteoff & ~15u)) + (byteoff & 15u);
    *(__nv_bfloat16*)(hi + off) = h;
    *(__nv_bfloat16*)(lo + off) = l;
}

// ---------------- tcgen05 NT GEMM: clustered bulk pipeline, bf16 split ------
// Cluster (1,2,1): the two CTAs of a pair share the SAME B tiles. Each member
// bulk-loads HALF of each B block and multicasts it to both -> per-CTA LTS
// traffic 96->64 KB/chunk. MMA completion arrives on BOTH CTAs' empty bars
// (commit multicast) so neither side's smem slot is reused while in use.
// 160 threads: warps 0-3 = epilogue, warp 4 = pipeline.
// C = Ahi*Bhi^T + Ahi*Blo^T + Alo*Bhi^T into TMEM fp32.
// zmode==1: grid.z in {0,1} selects B + bf16-split out. zmode==0: batched fp32.
__global__ void __launch_bounds__(160)
tc_gemm(const char* __restrict__ Ahi, const char* __restrict__ Alo,
        const char* __restrict__ B0hi, const char* __restrict__ B0lo,
        const char* __restrict__ B1hi, const char* __restrict__ B1lo,
        float* __restrict__ Cf,
        char* __restrict__ C0hi, char* __restrict__ C0lo,
        char* __restrict__ C1hi, char* __restrict__ C1lo,
        const float* __restrict__ bias,
        int kBlocks, int ldc, long strideC, int zmode)
{
#if HAS_TCGEN05
    constexpr int A_BYTES = TILE_M * 128;                 // 16 KB
    constexpr int B_BYTES = TN * 128;                     // 32 KB
    constexpr int BH      = B_BYTES / 2;                  // 16 KB half
    constexpr int STAGE   = 2 * A_BYTES + 2 * B_BYTES;    // 96 KB
    constexpr uint32_t IDESC =
        (1u<<4) | (1u<<7) | (1u<<10) | ((TN/8)<<17) | ((TILE_M/16)<<24);
    constexpr uint16_t MASK2 = 0x3;

    extern __shared__ char smem_raw[];
    const uint32_t raw = smem_u32(smem_raw);
    const uint32_t tileBase = (raw + 1023u) & ~1023u;
    const uint32_t barBase  = tileBase + ST * STAGE;   // full[s]@+16s, empty@+16s+8
    const uint32_t doneBar  = barBase + ST * 16;
    const uint32_t tmemSlot = doneBar + 16;

    const int tid = threadIdx.x, wid = tid >> 5, lane = tid & 31;
    const uint32_t rank = ctarank();       // 0/1 within y-pair
    int z = blockIdx.z;
    const int m0 = blockIdx.y * TILE_M;
    const int n0 = blockIdx.x * TN;

    const char* Bhi = B0hi; const char* Blo = B0lo;
    char* Chi = C0hi; char* Clo = C0lo;
    int rowTile = 128;                      // bf16-out layout tile rows
    if (zmode == 1) {
        if (z == 1) { Bhi = B1hi; Blo = B1lo; Chi = C1hi; Clo = C1lo; rowTile = 256; }
        z = 0;
    }
    const int aRow0 = z * S_ + m0;
    const int bRow0 = z * S_ + n0;

    if (wid == 0) {
        asm volatile("tcgen05.alloc.cta_group::1.sync.aligned.shared::cta.b32 [%0], %1;"
                     :: "r"(tmemSlot), "r"(TN) : "memory");
        asm volatile("tcgen05.relinquish_alloc_permit.cta_group::1.sync.aligned;");
    }
    if (tid == 0) {
#pragma unroll
        for (int s = 0; s < ST; s++) {
            mbar_init(barBase + s * 16, 1);        // full: expect_tx arrive + tx
            mbar_init(barBase + s * 16 + 8, 2);    // empty: commit from BOTH CTAs
        }
        mbar_init(doneBar, 1);
    }
    __syncthreads();
    // All cluster barriers must be live before any peer multicast targets them.
    CLUSTER_SYNC();
    uint32_t tmem;
    asm volatile("ld.shared.b32 %0, [%1];" : "=r"(tmem) : "r"(tmemSlot));

    if (wid == 4) {
        const int chunks = kBlocks;
        auto issue_load = [&](int c, int s) {
            uint32_t sA = tileBase + s * STAGE;
            size_t ab = ((size_t)(aRow0 >> 7) * kBlocks + c) * (size_t)A_BYTES;
            size_t bb = ((size_t)(bRow0 >> 8) * kBlocks + c) * (size_t)B_BYTES;
            uint32_t fb = barBase + s * 16;
            // tx per CTA: A 32K (own) + own B-half mc 32K + peer B-half mc 32K
            mbar_expect_tx(fb, STAGE);
            bulk_g2s(sA,           Ahi + ab, A_BYTES, fb);
            bulk_g2s(sA + A_BYTES, Alo + ab, A_BYTES, fb);
            uint32_t ho = rank * (uint32_t)BH;
            bulk_g2s_mc(sA + 2*A_BYTES + ho,           Bhi + bb + ho, BH, fb, MASK2);
            bulk_g2s_mc(sA + 2*A_BYTES + B_BYTES + ho, Blo + bb + ho, BH, fb, MASK2);
        };
        if (elect_one()) {
#pragma unroll
            for (int s = 0; s < ST; s++)
                if (s < chunks) issue_load(s, s);
        }
        for (int m = 0; m < chunks; m++) {
            int s = m % ST;
            mbar_wait(barBase + s * 16, (m / ST) & 1);
            if (elect_one()) {
                uint32_t sA = tileBase + s * STAGE;
                uint64_t dAh = make_desc(sA);
                uint64_t dAl = make_desc(sA + A_BYTES);
                uint64_t dBh = make_desc(sA + 2*A_BYTES);
                uint64_t dBl = make_desc(sA + 2*A_BYTES + B_BYTES);
#pragma unroll
                for (int km = 0; km < 4; km++)
                    mma_bf16_ss(tmem, dAh + km*2, dBh + km*2, IDESC, !(m == 0 && km == 0));
#pragma unroll
                for (int km = 0; km < 4; km++)
                    mma_bf16_ss(tmem, dAh + km*2, dBl + km*2, IDESC, true);
#pragma unroll
                for (int km = 0; km < 4; km++)
                    mma_bf16_ss(tmem, dAl + km*2, dBh + km*2, IDESC, true);
                // arrive on BOTH CTAs' empty[s] when this MMA group completes
                tc_commit_mc(barBase + s * 16 + 8, MASK2);
            }
            int nx = m + ST;
            if (nx < chunks) {
                // both CTAs' chunk-m MMAs must be done before slot s refill
                mbar_wait(barBase + s * 16 + 8, (m / ST) & 1);
                if (elect_one()) issue_load(nx, s);
            }
        }
        if (elect_one()) tc_commit(doneBar);   // completion of ALL prior MMAs
    }

    if (wid < 4) {
        mbar_wait(doneBar, 0);
        asm volatile("tcgen05.fence::after_thread_sync;" ::: "memory");
        const float bv = bias ? bias[0] : 0.f;
        const int row = m0 + wid * 32 + lane;
#pragma unroll
        for (int pass = 0; pass < TN / 32; pass++) {
            uint32_t r[32];
            asm volatile(
                "tcgen05.ld.sync.aligned.32x32b.x32.b32 "
                "{%0,%1,%2,%3,%4,%5,%6,%7,%8,%9,%10,%11,%12,%13,%14,%15,"
                "%16,%17,%18,%19,%20,%21,%22,%23,%24,%25,%26,%27,%28,%29,%30,%31}, [%32];"
                : "=r"(r[0]), "=r"(r[1]), "=r"(r[2]), "=r"(r[3]), "=r"(r[4]), "=r"(r[5]),
                  "=r"(r[6]), "=r"(r[7]), "=r"(r[8]), "=r"(r[9]), "=r"(r[10]), "=r"(r[11]),
                  "=r"(r[12]), "=r"(r[13]), "=r"(r[14]), "=r"(r[15]), "=r"(r[16]), "=r"(r[17]),
                  "=r"(r[18]), "=r"(r[19]), "=r"(r[20]), "=r"(r[21]), "=r"(r[22]), "=r"(r[23]),
                  "=r"(r[24]), "=r"(r[25]), "=r"(r[26]), "=r"(r[27]), "=r"(r[28]), "=r"(r[29]),
                  "=r"(r[30]), "=r"(r[31])
                : "r"(tmem + pass * 32));
            asm volatile("tcgen05.wait::ld.sync.aligned;" ::: "memory");

            if (Cf) {
                float* dst = Cf + (size_t)z * strideC + (size_t)row * ldc + n0 + pass * 32;
#pragma unroll
                for (int g = 0; g < 8; g++) {
                    float4 v = make_float4(__uint_as_float(r[g*4+0]) + bv,
                                           __uint_as_float(r[g*4+1]) + bv,
                                           __uint_as_float(r[g*4+2]) + bv,
                                           __uint_as_float(r[g*4+3]) + bv);
                    *(float4*)(dst + g * 4) = v;
                }
            } else {
                // bf16 split out, tiled+swizzled (feeds GEMM3's bulk loads)
#pragma unroll
                for (int g = 0; g < 4; g++) {
                    int r8 = n0 + pass * 32 + g * 8;   // col base, multiple of 8
                    union { __nv_bfloat16 h[8]; uint4 u; } ph, pl;
#pragma unroll
                    for (int e = 0; e < 8; e++) {
                        float v = __uint_as_float(r[g * 8 + e]);
                        split1(v, ph.h[e], pl.h[e]);
                    }
                    size_t off = ((size_t)(row / rowTile) * (R_ / 64) + (r8 >> 6))
                                   * ((size_t)rowTile * 128)
                               + SW128((uint32_t)(row % rowTile) * 128 + (uint32_t)(r8 & 63) * 2);
                    *(uint4*)(Chi + off) = ph.u;
                    *(uint4*)(Clo + off) = pl.u;
                }
            }
        }
        asm volatile("tcgen05.fence::before_thread_sync;" ::: "memory");
    }
    __syncthreads();
    if (wid == 0) {
        asm volatile("tcgen05.dealloc.cta_group::1.sync.aligned.b32 %0, %1;"
                     :: "r"(tmem), "r"(TN) : "memory");
    }
    // No CTA may exit while a peer multicast targeting its SMEM is in flight.
    CLUSTER_SYNC();
#endif  // HAS_TCGEN05
}

// ---------------- launch ----------------
extern "C" void kernel_launch(void* const* d_in, const int* in_sizes, int n_in,
                              void* d_out, int out_size)
{
    const float* batch  = (const float*)d_in[0];   // (B,S,D)
    const float* proj_L = (const float*)d_in[1];   // (D,R)
    const float* proj_R = (const float*)d_in[2];   // (R,D)
    const float* bias   = (const float*)d_in[3];   // (1,)
    float* out = (float*)d_out;                    // (B,S,S)

    char *batch_hi, *batch_lo, *LT_hi, *LT_lo, *PR_hi, *PR_lo;
    char *left_hi, *left_lo, *right_hi, *right_lo;
    cudaGetSymbolAddress((void**)&batch_hi, g_batch_hi);
    cudaGetSymbolAddress((void**)&batch_lo, g_batch_lo);
    cudaGetSymbolAddress((void**)&LT_hi, g_LT_hi);
    cudaGetSymbolAddress((void**)&LT_lo, g_LT_lo);
    cudaGetSymbolAddress((void**)&PR_hi, g_PR_hi);
    cudaGetSymbolAddress((void**)&PR_lo, g_PR_lo);
    cudaGetSymbolAddress((void**)&left_hi, g_left_hi);
    cudaGetSymbolAddress((void**)&left_lo, g_left_lo);
    cudaGetSymbolAddress((void**)&right_hi, g_right_hi);
    cudaGetSymbolAddress((void**)&right_lo, g_right_lo);

    constexpr int SMEM = 1024 + ST * (2*16384 + 2*32768) + 256;   // ~198 KB
    cudaFuncSetAttribute(tc_gemm, cudaFuncAttributeMaxDynamicSharedMemorySize, SMEM);

    // 1) input conversions -> tiled/swizzled bf16 hi/lo
    split_tiled<128, D_><<<(B_*S_*D_/4)/256, 256>>>((const float4*)batch, batch_hi, batch_lo);
    split_tiled<256, D_><<<(R_*D_/4)/256, 256>>>((const float4*)proj_R, PR_hi, PR_lo);
    tsplit_kernel<<<dim3(R_/32, D_/32), dim3(32, 32)>>>(proj_L, LT_hi, LT_lo);

    cudaLaunchAttribute attrs[1];
    attrs[0].id = cudaLaunchAttributeClusterDimension;
    attrs[0].val.clusterDim = {1, 2, 1};

    // 2+3) fused: z=0 -> left = batch @ LT^T, z=1 -> right = batch @ PR^T.
    //      M=8192, N=256, K=1024. Cluster (1,2,1): y-pairs share B via multicast.
    {
        cudaLaunchConfig_t cfg = {};
        cfg.gridDim = {1, (B_*S_)/TILE_M, 2};
        cfg.blockDim = {160, 1, 1};
        cfg.dynamicSmemBytes = SMEM;
        cfg.attrs = attrs;
        cfg.numAttrs = 1;
        cudaLaunchKernelEx(&cfg, tc_gemm,
            (const char*)batch_hi, (const char*)batch_lo,
            (const char*)LT_hi, (const char*)LT_lo,
            (const char*)PR_hi, (const char*)PR_lo,
            (float*)nullptr,
            left_hi, left_lo, right_hi, right_lo,
            (const float*)nullptr, D_/KCH, 0, (long)0, 1);
    }

    // 4) logits[b] = left[b] @ right[b]^T + bias  (batched, M=N=1024, K=256)
    //    y-pairs share each B tile via multicast.
    {
        cudaLaunchConfig_t cfg = {};
        cfg.gridDim = {S_/TN, S_/TILE_M, B_};
        cfg.blockDim = {160, 1, 1};
        cfg.dynamicSmemBytes = SMEM;
        cfg.attrs = attrs;
        cfg.numAttrs = 1;
        cudaLaunchKernelEx(&cfg, tc_gemm,
            (const char*)left_hi, (const char*)left_lo,
            (const char*)right_hi, (const char*)right_lo,
            (const char*)nullptr, (const char*)nullptr,
            out,
            (char*)nullptr, (char*)nullptr, (char*)nullptr, (char*)nullptr,
            bias, R_/KCH, S_, (long)S_*S_, 0);
    }
}

// round 14
// speedup vs baseline: 1.6324x; 1.6324x over previous
#include <cuda_runtime.h>
#include <cuda_fp16.h>
#include <cstdint>

// tcgen05 is arch-SPECIFIC (sm_103a): guard device code so the harness's plain
// compute_103 PTX pass compiles. The sm_103a cubin is what actually runs.
#if defined(__CUDA_ARCH__) && (defined(__CUDA_ARCH_FEAT_SM103_ALL) || \
    defined(__CUDA_ARCH_FEAT_SM100_ALL) || defined(__CUDA_ARCH_SPECIFIC__) || \
    defined(__CUDA_ARCH_FAMILY_SPECIFIC__))
#define HAS_TCGEN05 1
#else
#define HAS_TCGEN05 0
#endif

// Problem dims (fixed)
#define B_  8
#define S_  1024
#define D_  1024
#define R_  256

#define TILE_M 128
#define TN     256
#define KCH    64          // fp16 K per chunk = 128B SW128 row

// ---------------- tiled scratch (device globals; no allocs allowed) ----------
// Single fp16 stream, tile-contiguous + SW128-pre-swizzled:
//   A layout: [row/128][kc][128 rows x 128B]  (16 KB blocks)
//   B layout: [row/256][kc][256 rows x 128B]  (32 KB blocks)
__device__ char g_batch_h[(size_t)B_*S_*D_*2];    // A for GEMM1/2 (16 MB)
__device__ char g_LT_h[(size_t)R_*D_*2];          // B for GEMM1 (proj_L^T)
__device__ char g_PR_h[(size_t)R_*D_*2];          // B for GEMM2 (proj_R)
__device__ char g_left_h[(size_t)B_*S_*R_*2];     // A for GEMM3 (4 MB)
__device__ char g_right_h[(size_t)B_*S_*R_*2];    // B for GEMM3

// ---------------- PTX helpers ----------------
__device__ __forceinline__ uint32_t smem_u32(const void* p) {
    uint32_t a;
    asm("{ .reg .u64 t; cvta.to.shared.u64 t, %1; cvt.u32.u64 %0, t; }" : "=r"(a) : "l"(p));
    return a;
}
#define SW128(off) ((off) ^ (((off) >> 3) & 0x70))

__device__ __forceinline__ void mbar_init(uint32_t a, uint32_t cnt) {
    asm volatile("mbarrier.init.shared.b64 [%0], %1;" :: "r"(a), "r"(cnt) : "memory");
}
__device__ __forceinline__ void mbar_wait(uint32_t a, uint32_t parity) {
    asm volatile(
        "{\n\t.reg .pred P;\n\t"
        "WL_%=:\n\t"
        "mbarrier.try_wait.parity.acquire.cta.shared::cta.b64 P, [%0], %1, 0x989680;\n\t"
        "@P bra WD_%=;\n\t"
        "bra WL_%=;\n\t"
        "WD_%=:\n\t}"
        :: "r"(a), "r"(parity) : "memory");
}

#if HAS_TCGEN05
__device__ __forceinline__ uint32_t elect_one() {
    uint32_t p;
    asm volatile("{ .reg .pred p; elect.sync _|p, 0xFFFFFFFF; selp.b32 %0,1,0,p; }" : "=r"(p));
    return p;
}
__device__ __forceinline__ void mbar_expect_tx(uint32_t mbar, uint32_t bytes) {
    asm volatile("mbarrier.arrive.expect_tx.shared.b64 _, [%0], %1;"
                 :: "r"(mbar), "r"(bytes) : "memory");
}
// 1D bulk copy global->smem, completion via mbarrier tx-count (SASS: UBLKCP)
__device__ __forceinline__ void bulk_g2s(uint32_t sdst, const void* gsrc,
                                         uint32_t bytes, uint32_t mbar) {
    asm volatile(
        "cp.async.bulk.shared::cluster.global.mbarrier::complete_tx::bytes "
        "[%0], [%1], %2, [%3];"
        :: "r"(sdst), "l"(gsrc), "r"(bytes), "r"(mbar) : "memory");
}

// SW128 K-major SMEM descriptor (layout=2, version=1, SBO=64, LBO=1)
__device__ __forceinline__ uint64_t make_desc(uint32_t addr) {
    const uint64_t base = (uint64_t(2) << 61) | (uint64_t(1) << 46)
                        | (uint64_t(64) << 32) | (uint64_t(1) << 16);
    return base | ((uint64_t)(addr >> 4) & 0x3FFF);
}
// fp16 SS MMA, cta_group::1, kind::f16, fp32 accum.
// idesc: dtype F32(1<<4) | atype F16(0) | btype F16(0) | (N/8)<<17 | (M/16)<<24
__device__ __forceinline__ void mma_f16_ss(uint32_t d, uint64_t ad, uint64_t bd,
                                           uint32_t idesc, bool acc) {
    uint32_t en = acc ? 1u : 0u, z = 0u;
    asm volatile(
        "{\n\t.reg .pred p;\n\tsetp.ne.u32 p, %5, 0;\n\t"
        "tcgen05.mma.cta_group::1.kind::f16 [%0], %1, %2, %3, {%4,%4,%4,%4}, p;\n\t}"
        :: "r"(d), "l"(ad), "l"(bd), "r"(idesc), "r"(z), "r"(en) : "memory");
}
__device__ __forceinline__ void tc_commit(uint32_t mbar) {
    asm volatile(
        "tcgen05.commit.cta_group::1.mbarrier::arrive::one.shared::cluster.b64 [%0];"
        :: "r"(mbar) : "memory");
}
#endif  // HAS_TCGEN05

// ---------------- conversion kernels (emit tiled+swizzled fp16) -------------
// Row-major (rows x K) fp32 -> tiled/swizzled fp16. TS = tile row count.
template <int TS, int K>
__global__ void conv_tiled(const float4* __restrict__ src, char* __restrict__ dst) {
    int i = blockIdx.x * blockDim.x + threadIdx.x;
    int idx4 = i * 4;
    int m = idx4 / K, d = idx4 % K;
    float4 v = src[i];
    __half h[4];
    h[0] = __float2half_rn(v.x); h[1] = __float2half_rn(v.y);
    h[2] = __float2half_rn(v.z); h[3] = __float2half_rn(v.w);
    uint32_t byteoff = (uint32_t)(d & 63) * 2;                  // multiple of 8
    uint32_t inb = SW128((uint32_t)(m % TS) * 128 + (byteoff & ~15u)) + (byteoff & 15u);
    size_t off = ((size_t)(m / TS) * (K / 64) + (d >> 6)) * ((size_t)TS * 128) + inb;
    *(uint64_t*)(dst + off) = *(const uint64_t*)h;
}

// proj_L (D,R) -> transposed (R,D) tiled/swizzled fp16 B layout (TS=256)
__global__ void tconv_kernel(const float* __restrict__ src, char* __restrict__ dst) {
    __shared__ float t[32][33];
    int tx = threadIdx.x, ty = threadIdx.y;
    int d0 = blockIdx.y * 32, r0 = blockIdx.x * 32;
    t[ty][tx] = src[(size_t)(d0 + ty) * R_ + r0 + tx];
    __syncthreads();
    float v = t[tx][ty];                // out[r0+ty][d0+tx]
    int r = r0 + ty, d = d0 + tx;
    uint32_t byteoff = (uint32_t)(d & 63) * 2;
    size_t off = ((size_t)(r >> 8) * (D_ / 64) + (d >> 6)) * (size_t)(256 * 128)
               + SW128((uint32_t)(r & 255) * 128 + (byteoff & ~15u)) + (byteoff & 15u);
    *(__half*)(dst + off) = __float2half_rn(v);
}

// ---------------- tcgen05 NT GEMM: fp16 single-term, bulk-copy pipeline -----
// 160 threads: warps 0-3 = epilogue, warp 4 = pipeline (bulk loads + MMA).
// Chunk = K-slice of 64; blocks A|B pre-swizzled in GMEM -> 2 bulk copies per
// chunk into one 48KB stage. Single fp16 MMA term into TMEM fp32 accumulator.
// zmode==1: grid.z in {0,1} selects B + fp16-tiled out (left: 128-row layout,
//           right: 256-row layout). zmode==0: grid.z = batch (GEMM3, fp32 out).
template <int ST>
__global__ void __launch_bounds__(160)
tc_gemm(const char* __restrict__ Ap,
        const char* __restrict__ B0, const char* __restrict__ B1,
        float* __restrict__ Cf,
        char* __restrict__ C0, char* __restrict__ C1,
        const float* __restrict__ bias,
        int kBlocks, int ldc, long strideC, int zmode)
{
#if HAS_TCGEN05
    constexpr int A_BYTES = TILE_M * 128;                 // 16 KB
    constexpr int B_BYTES = TN * 128;                     // 32 KB
    constexpr int STAGE   = A_BYTES + B_BYTES;            // 48 KB
    constexpr uint32_t IDESC =
        (1u<<4) | ((TN/8)<<17) | ((TILE_M/16)<<24);       // fp16 in, fp32 acc

    extern __shared__ char smem_raw[];
    const uint32_t raw = smem_u32(smem_raw);
    const uint32_t tileBase = (raw + 1023u) & ~1023u;
    const uint32_t barBase  = tileBase + ST * STAGE;   // full[s]@+16s, empty@+16s+8
    const uint32_t doneBar  = barBase + ST * 16;
    const uint32_t tmemSlot = doneBar + 16;

    const int tid = threadIdx.x, wid = tid >> 5, lane = tid & 31;
    int z = blockIdx.z;
    const int m0 = blockIdx.y * TILE_M;
    const int n0 = blockIdx.x * TN;

    const char* Bp = B0;
    char* Co = C0;
    int rowTile = 128;                      // fp16-out layout tile rows
    if (zmode == 1) {
        if (z == 1) { Bp = B1; Co = C1; rowTile = 256; }
        z = 0;
    }
    const int aRow0 = z * S_ + m0;
    const int bRow0 = z * S_ + n0;

    if (wid == 0) {
        asm volatile("tcgen05.alloc.cta_group::1.sync.aligned.shared::cta.b32 [%0], %1;"
                     :: "r"(tmemSlot), "r"(TN) : "memory");
        asm volatile("tcgen05.relinquish_alloc_permit.cta_group::1.sync.aligned;");
    }
    if (tid == 0) {
#pragma unroll
        for (int s = 0; s < ST; s++) {
            mbar_init(barBase + s * 16, 1);        // full: expect_tx arrive + tx
            mbar_init(barBase + s * 16 + 8, 1);    // empty: one MMA commit
        }
        mbar_init(doneBar, 1);
    }
    __syncthreads();
    uint32_t tmem;
    asm volatile("ld.shared.b32 %0, [%1];" : "=r"(tmem) : "r"(tmemSlot));

    if (wid == 4) {
        const int chunks = kBlocks;
        auto issue_load = [&](int c, int s) {
            uint32_t sA = tileBase + s * STAGE;
            size_t ab = ((size_t)(aRow0 >> 7) * kBlocks + c) * (size_t)A_BYTES;
            size_t bb = ((size_t)(bRow0 >> 8) * kBlocks + c) * (size_t)B_BYTES;
            uint32_t fb = barBase + s * 16;
            mbar_expect_tx(fb, STAGE);
            bulk_g2s(sA,           Ap + ab, A_BYTES, fb);
            bulk_g2s(sA + A_BYTES, Bp + bb, B_BYTES, fb);
        };
        if (elect_one()) {
#pragma unroll
            for (int s = 0; s < ST; s++)
                if (s < chunks) issue_load(s, s);
        }
        for (int m = 0; m < chunks; m++) {
            int s = m % ST;
            mbar_wait(barBase + s * 16, (m / ST) & 1);
            if (elect_one()) {
                uint32_t sA = tileBase + s * STAGE;
                uint64_t dA = make_desc(sA);
                uint64_t dB = make_desc(sA + A_BYTES);
#pragma unroll
                for (int km = 0; km < 4; km++)
                    mma_f16_ss(tmem, dA + km*2, dB + km*2, IDESC, !(m == 0 && km == 0));
                tc_commit(barBase + s * 16 + 8);
            }
            int nx = m + ST;
            if (nx < chunks) {
                // slot s reuse: MMA(m) completion gates refill of slot s
                mbar_wait(barBase + s * 16 + 8, (m / ST) & 1);
                if (elect_one()) issue_load(nx, s);
            }
        }
        if (elect_one()) tc_commit(doneBar);   // completion of ALL prior MMAs
    }

    if (wid < 4) {
        mbar_wait(doneBar, 0);
        asm volatile("tcgen05.fence::after_thread_sync;" ::: "memory");
        const float bv = bias ? bias[0] : 0.f;
        const int row = m0 + wid * 32 + lane;
#pragma unroll
        for (int pass = 0; pass < TN / 32; pass++) {
            uint32_t r[32];
            asm volatile(
                "tcgen05.ld.sync.aligned.32x32b.x32.b32 "
                "{%0,%1,%2,%3,%4,%5,%6,%7,%8,%9,%10,%11,%12,%13,%14,%15,"
                "%16,%17,%18,%19,%20,%21,%22,%23,%24,%25,%26,%27,%28,%29,%30,%31}, [%32];"
                : "=r"(r[0]), "=r"(r[1]), "=r"(r[2]), "=r"(r[3]), "=r"(r[4]), "=r"(r[5]),
                  "=r"(r[6]), "=r"(r[7]), "=r"(r[8]), "=r"(r[9]), "=r"(r[10]), "=r"(r[11]),
                  "=r"(r[12]), "=r"(r[13]), "=r"(r[14]), "=r"(r[15]), "=r"(r[16]), "=r"(r[17]),
                  "=r"(r[18]), "=r"(r[19]), "=r"(r[20]), "=r"(r[21]), "=r"(r[22]), "=r"(r[23]),
                  "=r"(r[24]), "=r"(r[25]), "=r"(r[26]), "=r"(r[27]), "=r"(r[28]), "=r"(r[29]),
                  "=r"(r[30]), "=r"(r[31])
                : "r"(tmem + pass * 32));
            asm volatile("tcgen05.wait::ld.sync.aligned;" ::: "memory");

            if (Cf) {
                float* dst = Cf + (size_t)z * strideC + (size_t)row * ldc + n0 + pass * 32;
#pragma unroll
                for (int g = 0; g < 8; g++) {
                    float4 v = make_float4(__uint_as_float(r[g*4+0]) + bv,
                                           __uint_as_float(r[g*4+1]) + bv,
                                           __uint_as_float(r[g*4+2]) + bv,
                                           __uint_as_float(r[g*4+3]) + bv);
                    *(float4*)(dst + g * 4) = v;
                }
            } else {
                // fp16 out, tiled+swizzled (feeds GEMM3's bulk loads)
#pragma unroll
                for (int g = 0; g < 4; g++) {
                    int r8 = n0 + pass * 32 + g * 8;   // col base, multiple of 8
                    union { __half h[8]; uint4 u; } ph;
#pragma unroll
                    for (int e = 0; e < 8; e++)
                        ph.h[e] = __float2half_rn(__uint_as_float(r[g * 8 + e]));
                    size_t off = ((size_t)(row / rowTile) * (R_ / 64) + (r8 >> 6))
                                   * ((size_t)rowTile * 128)
                               + SW128((uint32_t)(row % rowTile) * 128 + (uint32_t)(r8 & 63) * 2);
                    *(uint4*)(Co + off) = ph.u;
                }
            }
        }
        asm volatile("tcgen05.fence::before_thread_sync;" ::: "memory");
    }
    __syncthreads();
    if (wid == 0) {
        asm volatile("tcgen05.dealloc.cta_group::1.sync.aligned.b32 %0, %1;"
                     :: "r"(tmem), "r"(TN) : "memory");
    }
#endif  // HAS_TCGEN05
}

// ---------------- launch ----------------
extern "C" void kernel_launch(void* const* d_in, const int* in_sizes, int n_in,
                              void* d_out, int out_size)
{
    const float* batch  = (const float*)d_in[0];   // (B,S,D)
    const float* proj_L = (const float*)d_in[1];   // (D,R)
    const float* proj_R = (const float*)d_in[2];   // (R,D)
    const float* bias   = (const float*)d_in[3];   // (1,)
    float* out = (float*)d_out;                    // (B,S,S)

    char *batch_h, *LT_h, *PR_h, *left_h, *right_h;
    cudaGetSymbolAddress((void**)&batch_h, g_batch_h);
    cudaGetSymbolAddress((void**)&LT_h, g_LT_h);
    cudaGetSymbolAddress((void**)&PR_h, g_PR_h);
    cudaGetSymbolAddress((void**)&left_h, g_left_h);
    cudaGetSymbolAddress((void**)&right_h, g_right_h);

    constexpr int STAGE_B = TILE_M*128 + TN*128;                  // 48 KB
    constexpr int SMEM_4 = 1024 + 4 * STAGE_B + 256;              // ~193 KB, 1 CTA/SM
    constexpr int SMEM_2 = 1024 + 2 * STAGE_B + 256;              // ~97 KB, 2 CTA/SM
    cudaFuncSetAttribute(tc_gemm<4>, cudaFuncAttributeMaxDynamicSharedMemorySize, SMEM_4);
    cudaFuncSetAttribute(tc_gemm<2>, cudaFuncAttributeMaxDynamicSharedMemorySize, SMEM_2);

    // 1) input conversions -> tiled/swizzled fp16
    conv_tiled<128, D_><<<(B_*S_*D_/4)/256, 256>>>((const float4*)batch, batch_h);
    conv_tiled<256, D_><<<(R_*D_/4)/256, 256>>>((const float4*)proj_R, PR_h);
    tconv_kernel<<<dim3(R_/32, D_/32), dim3(32, 32)>>>(proj_L, LT_h);

    // 2+3) fused: z=0 -> left = batch @ LT^T (128-row-tiled out),
    //             z=1 -> right = batch @ PR^T (256-row-tiled out).
    //      M=8192, N=256, K=1024; ST=4 pipeline, 1 CTA/SM.
    tc_gemm<4><<<dim3(1, (B_*S_)/TILE_M, 2), 160, SMEM_4>>>(
        batch_h, LT_h, PR_h,
        nullptr, left_h, right_h,
        nullptr, /*kBlocks=*/D_/KCH, 0, 0, /*zmode=*/1);

    // 4) logits[b] = left[b] @ right[b]^T + bias  (batched, M=N=1024, K=256)
    //    ST=2 -> 2 CTAs/SM, 256 CTAs in one wave; cross-CTA epilogue overlap.
    tc_gemm<2><<<dim3(S_/TN, S_/TILE_M, B_), 160, SMEM_2>>>(
        left_h, right_h, nullptr,
        out, nullptr, nullptr,
        bias, /*kBlocks=*/R_/KCH, S_, (long)S_*S_, /*zmode=*/0);
}

// round 15
// speedup vs baseline: 1.6723x; 1.0245x over previous
#include <cuda_runtime.h>
#include <cuda_fp16.h>
#include <cstdint>

// tcgen05 is arch-SPECIFIC (sm_103a): guard device code so the harness's plain
// compute_103 PTX pass compiles. The sm_103a cubin is what actually runs.
#if defined(__CUDA_ARCH__) && (defined(__CUDA_ARCH_FEAT_SM103_ALL) || \
    defined(__CUDA_ARCH_FEAT_SM100_ALL) || defined(__CUDA_ARCH_SPECIFIC__) || \
    defined(__CUDA_ARCH_FAMILY_SPECIFIC__))
#define HAS_TCGEN05 1
#else
#define HAS_TCGEN05 0
#endif

// Problem dims (fixed)
#define B_  8
#define S_  1024
#define D_  1024
#define R_  256

#define TILE_M 128
#define TN     256
#define KCH    64          // fp16 K per chunk = 128B SW128 row

// ---------------- tiled scratch (device globals; no allocs allowed) ----------
// Single fp16 stream, tile-contiguous + SW128-pre-swizzled:
//   A layout: [row/128][kc][128 rows x 128B]  (16 KB blocks)
//   B layout: [row/256][kc][256 rows x 128B]  (32 KB blocks)
__device__ char g_batch_h[(size_t)B_*S_*D_*2];    // A for GEMM1/2 (16 MB)
__device__ char g_LT_h[(size_t)R_*D_*2];          // B for GEMM1 (proj_L^T)
__device__ char g_PR_h[(size_t)R_*D_*2];          // B for GEMM2 (proj_R)
__device__ char g_left_h[(size_t)B_*S_*R_*2];     // A for GEMM3 (4 MB)
__device__ char g_right_h[(size_t)B_*S_*R_*2];    // B for GEMM3

// ---------------- PTX helpers ----------------
__device__ __forceinline__ uint32_t smem_u32(const void* p) {
    uint32_t a;
    asm("{ .reg .u64 t; cvta.to.shared.u64 t, %1; cvt.u32.u64 %0, t; }" : "=r"(a) : "l"(p));
    return a;
}
#define SW128(off) ((off) ^ (((off) >> 3) & 0x70))

__device__ __forceinline__ void mbar_init(uint32_t a, uint32_t cnt) {
    asm volatile("mbarrier.init.shared.b64 [%0], %1;" :: "r"(a), "r"(cnt) : "memory");
}
__device__ __forceinline__ void mbar_wait(uint32_t a, uint32_t parity) {
    asm volatile(
        "{\n\t.reg .pred P;\n\t"
        "WL_%=:\n\t"
        "mbarrier.try_wait.parity.acquire.cta.shared::cta.b64 P, [%0], %1, 0x989680;\n\t"
        "@P bra WD_%=;\n\t"
        "bra WL_%=;\n\t"
        "WD_%=:\n\t}"
        :: "r"(a), "r"(parity) : "memory");
}

#if HAS_TCGEN05
__device__ __forceinline__ uint32_t elect_one() {
    uint32_t p;
    asm volatile("{ .reg .pred p; elect.sync _|p, 0xFFFFFFFF; selp.b32 %0,1,0,p; }" : "=r"(p));
    return p;
}
__device__ __forceinline__ void mbar_expect_tx(uint32_t mbar, uint32_t bytes) {
    asm volatile("mbarrier.arrive.expect_tx.shared.b64 _, [%0], %1;"
                 :: "r"(mbar), "r"(bytes) : "memory");
}
// 1D bulk copy global->smem, completion via mbarrier tx-count (SASS: UBLKCP)
__device__ __forceinline__ void bulk_g2s(uint32_t sdst, const void* gsrc,
                                         uint32_t bytes, uint32_t mbar) {
    asm volatile(
        "cp.async.bulk.shared::cluster.global.mbarrier::complete_tx::bytes "
        "[%0], [%1], %2, [%3];"
        :: "r"(sdst), "l"(gsrc), "r"(bytes), "r"(mbar) : "memory");
}

// SW128 K-major SMEM descriptor (layout=2, version=1, SBO=64, LBO=1)
__device__ __forceinline__ uint64_t make_desc(uint32_t addr) {
    const uint64_t base = (uint64_t(2) << 61) | (uint64_t(1) << 46)
                        | (uint64_t(64) << 32) | (uint64_t(1) << 16);
    return base | ((uint64_t)(addr >> 4) & 0x3FFF);
}
// fp16 SS MMA, cta_group::1, kind::f16, fp32 accum.
__device__ __forceinline__ void mma_f16_ss(uint32_t d, uint64_t ad, uint64_t bd,
                                           uint32_t idesc, bool acc) {
    uint32_t en = acc ? 1u : 0u, z = 0u;
    asm volatile(
        "{\n\t.reg .pred p;\n\tsetp.ne.u32 p, %5, 0;\n\t"
        "tcgen05.mma.cta_group::1.kind::f16 [%0], %1, %2, %3, {%4,%4,%4,%4}, p;\n\t}"
        :: "r"(d), "l"(ad), "l"(bd), "r"(idesc), "r"(z), "r"(en) : "memory");
}
__device__ __forceinline__ void tc_commit(uint32_t mbar) {
    asm volatile(
        "tcgen05.commit.cta_group::1.mbarrier::arrive::one.shared::cluster.b64 [%0];"
        :: "r"(mbar) : "memory");
}
#endif  // HAS_TCGEN05

// ---------------- conversion kernels (emit tiled+swizzled fp16) -------------
// Row-major (rows x K) fp32 -> tiled/swizzled fp16. TS = tile row count.
template <int TS, int K>
__global__ void conv_tiled(const float4* __restrict__ src, char* __restrict__ dst) {
    int i = blockIdx.x * blockDim.x + threadIdx.x;
    int idx4 = i * 4;
    int m = idx4 / K, d = idx4 % K;
    float4 v = src[i];
    __half h[4];
    h[0] = __float2half_rn(v.x); h[1] = __float2half_rn(v.y);
    h[2] = __float2half_rn(v.z); h[3] = __float2half_rn(v.w);
    uint32_t byteoff = (uint32_t)(d & 63) * 2;                  // multiple of 8
    uint32_t inb = SW128((uint32_t)(m % TS) * 128 + (byteoff & ~15u)) + (byteoff & 15u);
    size_t off = ((size_t)(m / TS) * (K / 64) + (d >> 6)) * ((size_t)TS * 128) + inb;
    *(uint64_t*)(dst + off) = *(const uint64_t*)h;
}

// proj_L (D,R) -> transposed (R,D) tiled/swizzled fp16 B layout (TS=256)
__global__ void tconv_kernel(const float* __restrict__ src, char* __restrict__ dst) {
    __shared__ float t[32][33];
    int tx = threadIdx.x, ty = threadIdx.y;
    int d0 = blockIdx.y * 32, r0 = blockIdx.x * 32;
    t[ty][tx] = src[(size_t)(d0 + ty) * R_ + r0 + tx];
    __syncthreads();
    float v = t[tx][ty];                // out[r0+ty][d0+tx]
    int r = r0 + ty, d = d0 + tx;
    uint32_t byteoff = (uint32_t)(d & 63) * 2;
    size_t off = ((size_t)(r >> 8) * (D_ / 64) + (d >> 6)) * (size_t)(256 * 128)
               + SW128((uint32_t)(r & 255) * 128 + (byteoff & ~15u)) + (byteoff & 15u);
    *(__half*)(dst + off) = __float2half_rn(v);
}

// ---------------- tcgen05 NT GEMM: fp16 single-term, bulk-copy pipeline -----
// 160 threads: warps 0-3 = epilogue, warp 4 = pipeline (bulk loads + MMA).
// Chunk = K-slice of 64; blocks A|B pre-swizzled in GMEM -> 2 bulk copies per
// chunk into one 48KB stage. Single fp16 MMA term into TMEM fp32 accumulator.
// Refill is SHIFTED one iteration: in iter m we refill slot (m-1)%ST for
// chunk m-1+ST, gated on MMA(m-1) completion -- which has had a full
// iteration to drain, so the empty-wait is ~free (the R13 loop waited on
// MMA(m)'s own completion immediately after dispatch, serializing the drain).
// zmode==1: grid.z in {0,1} selects B + fp16-tiled out. zmode==0: batched fp32.
template <int ST>
__global__ void __launch_bounds__(160)
tc_gemm(const char* __restrict__ Ap,
        const char* __restrict__ B0, const char* __restrict__ B1,
        float* __restrict__ Cf,
        char* __restrict__ C0, char* __restrict__ C1,
        const float* __restrict__ bias,
        int kBlocks, int ldc, long strideC, int zmode)
{
#if HAS_TCGEN05
    constexpr int A_BYTES = TILE_M * 128;                 // 16 KB
    constexpr int B_BYTES = TN * 128;                     // 32 KB
    constexpr int STAGE   = A_BYTES + B_BYTES;            // 48 KB
    constexpr uint32_t IDESC =
        (1u<<4) | ((TN/8)<<17) | ((TILE_M/16)<<24);       // fp16 in, fp32 acc

    extern __shared__ char smem_raw[];
    const uint32_t raw = smem_u32(smem_raw);
    const uint32_t tileBase = (raw + 1023u) & ~1023u;
    const uint32_t barBase  = tileBase + ST * STAGE;   // full[s]@+16s, empty@+16s+8
    const uint32_t doneBar  = barBase + ST * 16;
    const uint32_t tmemSlot = doneBar + 16;

    const int tid = threadIdx.x, wid = tid >> 5, lane = tid & 31;
    int z = blockIdx.z;
    const int m0 = blockIdx.y * TILE_M;
    const int n0 = blockIdx.x * TN;

    const char* Bp = B0;
    char* Co = C0;
    int rowTile = 128;                      // fp16-out layout tile rows
    if (zmode == 1) {
        if (z == 1) { Bp = B1; Co = C1; rowTile = 256; }
        z = 0;
    }
    const int aRow0 = z * S_ + m0;
    const int bRow0 = z * S_ + n0;

    if (wid == 0) {
        asm volatile("tcgen05.alloc.cta_group::1.sync.aligned.shared::cta.b32 [%0], %1;"
                     :: "r"(tmemSlot), "r"(TN) : "memory");
        asm volatile("tcgen05.relinquish_alloc_permit.cta_group::1.sync.aligned;");
    }
    if (tid == 0) {
#pragma unroll
        for (int s = 0; s < ST; s++) {
            mbar_init(barBase + s * 16, 1);        // full: expect_tx arrive + tx
            mbar_init(barBase + s * 16 + 8, 1);    // empty: one MMA commit
        }
        mbar_init(doneBar, 1);
    }
    __syncthreads();
    uint32_t tmem;
    asm volatile("ld.shared.b32 %0, [%1];" : "=r"(tmem) : "r"(tmemSlot));

    if (wid == 4) {
        const int chunks = kBlocks;
        auto issue_load = [&](int c, int s) {
            uint32_t sA = tileBase + s * STAGE;
            size_t ab = ((size_t)(aRow0 >> 7) * kBlocks + c) * (size_t)A_BYTES;
            size_t bb = ((size_t)(bRow0 >> 8) * kBlocks + c) * (size_t)B_BYTES;
            uint32_t fb = barBase + s * 16;
            mbar_expect_tx(fb, STAGE);
            bulk_g2s(sA,           Ap + ab, A_BYTES, fb);
            bulk_g2s(sA + A_BYTES, Bp + bb, B_BYTES, fb);
        };
        if (elect_one()) {
#pragma unroll
            for (int s = 0; s < ST; s++)
                if (s < chunks) issue_load(s, s);
        }
        for (int m = 0; m < chunks; m++) {
            int s = m % ST;
            mbar_wait(barBase + s * 16, (m / ST) & 1);
            if (elect_one()) {
                uint32_t sA = tileBase + s * STAGE;
                uint64_t dA = make_desc(sA);
                uint64_t dB = make_desc(sA + A_BYTES);
#pragma unroll
                for (int km = 0; km < 4; km++)
                    mma_f16_ss(tmem, dA + km*2, dB + km*2, IDESC, !(m == 0 && km == 0));
                tc_commit(barBase + s * 16 + 8);
            }
            // Deferred refill: slot used by chunk m-1, for chunk m-1+ST.
            // MMA(m-1) completion gates it and has had one full iteration.
            if (m >= 1) {
                int pm = m - 1;
                int nx = pm + ST;
                if (nx < chunks) {
                    int sp = pm % ST;
                    mbar_wait(barBase + sp * 16 + 8, (pm / ST) & 1);
                    if (elect_one()) issue_load(nx, sp);
                }
            }
        }
        if (elect_one()) tc_commit(doneBar);   // completion of ALL prior MMAs
    }

    if (wid < 4) {
        mbar_wait(doneBar, 0);
        asm volatile("tcgen05.fence::after_thread_sync;" ::: "memory");
        const float bv = bias ? bias[0] : 0.f;
        const int row = m0 + wid * 32 + lane;
#pragma unroll
        for (int pass = 0; pass < TN / 32; pass++) {
            uint32_t r[32];
            asm volatile(
                "tcgen05.ld.sync.aligned.32x32b.x32.b32 "
                "{%0,%1,%2,%3,%4,%5,%6,%7,%8,%9,%10,%11,%12,%13,%14,%15,"
                "%16,%17,%18,%19,%20,%21,%22,%23,%24,%25,%26,%27,%28,%29,%30,%31}, [%32];"
                : "=r"(r[0]), "=r"(r[1]), "=r"(r[2]), "=r"(r[3]), "=r"(r[4]), "=r"(r[5]),
                  "=r"(r[6]), "=r"(r[7]), "=r"(r[8]), "=r"(r[9]), "=r"(r[10]), "=r"(r[11]),
                  "=r"(r[12]), "=r"(r[13]), "=r"(r[14]), "=r"(r[15]), "=r"(r[16]), "=r"(r[17]),
                  "=r"(r[18]), "=r"(r[19]), "=r"(r[20]), "=r"(r[21]), "=r"(r[22]), "=r"(r[23]),
                  "=r"(r[24]), "=r"(r[25]), "=r"(r[26]), "=r"(r[27]), "=r"(r[28]), "=r"(r[29]),
                  "=r"(r[30]), "=r"(r[31])
                : "r"(tmem + pass * 32));
            asm volatile("tcgen05.wait::ld.sync.aligned;" ::: "memory");

            if (Cf) {
                float* dst = Cf + (size_t)z * strideC + (size_t)row * ldc + n0 + pass * 32;
#pragma unroll
                for (int g = 0; g < 8; g++) {
                    float4 v = make_float4(__uint_as_float(r[g*4+0]) + bv,
                                           __uint_as_float(r[g*4+1]) + bv,
                                           __uint_as_float(r[g*4+2]) + bv,
                                           __uint_as_float(r[g*4+3]) + bv);
                    *(float4*)(dst + g * 4) = v;
                }
            } else {
                // fp16 out, tiled+swizzled (feeds GEMM3's bulk loads)
#pragma unroll
                for (int g = 0; g < 4; g++) {
                    int r8 = n0 + pass * 32 + g * 8;   // col base, multiple of 8
                    union { __half h[8]; uint4 u; } ph;
#pragma unroll
                    for (int e = 0; e < 8; e++)
                        ph.h[e] = __float2half_rn(__uint_as_float(r[g * 8 + e]));
                    size_t off = ((size_t)(row / rowTile) * (R_ / 64) + (r8 >> 6))
                                   * ((size_t)rowTile * 128)
                               + SW128((uint32_t)(row % rowTile) * 128 + (uint32_t)(r8 & 63) * 2);
                    *(uint4*)(Co + off) = ph.u;
                }
            }
        }
        asm volatile("tcgen05.fence::before_thread_sync;" ::: "memory");
    }
    __syncthreads();
    if (wid == 0) {
        asm volatile("tcgen05.dealloc.cta_group::1.sync.aligned.b32 %0, %1;"
                     :: "r"(tmem), "r"(TN) : "memory");
    }
#endif  // HAS_TCGEN05
}

// ---------------- launch ----------------
extern "C" void kernel_launch(void* const* d_in, const int* in_sizes, int n_in,
                              void* d_out, int out_size)
{
    const float* batch  = (const float*)d_in[0];   // (B,S,D)
    const float* proj_L = (const float*)d_in[1];   // (D,R)
    const float* proj_R = (const float*)d_in[2];   // (R,D)
    const float* bias   = (const float*)d_in[3];   // (1,)
    float* out = (float*)d_out;                    // (B,S,S)

    char *batch_h, *LT_h, *PR_h, *left_h, *right_h;
    cudaGetSymbolAddress((void**)&batch_h, g_batch_h);
    cudaGetSymbolAddress((void**)&LT_h, g_LT_h);
    cudaGetSymbolAddress((void**)&PR_h, g_PR_h);
    cudaGetSymbolAddress((void**)&left_h, g_left_h);
    cudaGetSymbolAddress((void**)&right_h, g_right_h);

    constexpr int STAGE_B = TILE_M*128 + TN*128;                  // 48 KB
    constexpr int SMEM_4 = 1024 + 4 * STAGE_B + 256;              // ~193 KB, 1 CTA/SM
    constexpr int SMEM_2 = 1024 + 2 * STAGE_B + 256;              // ~97 KB, 2 CTA/SM
    cudaFuncSetAttribute(tc_gemm<4>, cudaFuncAttributeMaxDynamicSharedMemorySize, SMEM_4);
    cudaFuncSetAttribute(tc_gemm<2>, cudaFuncAttributeMaxDynamicSharedMemorySize, SMEM_2);

    // 1) input conversions -> tiled/swizzled fp16
    conv_tiled<128, D_><<<(B_*S_*D_/4)/256, 256>>>((const float4*)batch, batch_h);
    conv_tiled<256, D_><<<(R_*D_/4)/256, 256>>>((const float4*)proj_R, PR_h);
    tconv_kernel<<<dim3(R_/32, D_/32), dim3(32, 32)>>>(proj_L, LT_h);

    // 2+3) fused: z=0 -> left = batch @ LT^T (128-row-tiled out),
    //             z=1 -> right = batch @ PR^T (256-row-tiled out).
    //      M=8192, N=256, K=1024; ST=4 pipeline, 1 CTA/SM.
    tc_gemm<4><<<dim3(1, (B_*S_)/TILE_M, 2), 160, SMEM_4>>>(
        batch_h, LT_h, PR_h,
        nullptr, left_h, right_h,
        nullptr, /*kBlocks=*/D_/KCH, 0, 0, /*zmode=*/1);

    // 4) logits[b] = left[b] @ right[b]^T + bias  (batched, M=N=1024, K=256)
    //    ST=2 -> 2 CTAs/SM, 256 CTAs in one wave; cross-CTA epilogue overlap.
    tc_gemm<2><<<dim3(S_/TN, S_/TILE_M, B_), 160, SMEM_2>>>(
        left_h, right_h, nullptr,
        out, nullptr, nullptr,
        bias, /*kBlocks=*/R_/KCH, S_, (long)S_*S_, /*zmode=*/0);
}